// round 9
// baseline (speedup 1.0000x reference)
#include <cuda_runtime.h>

#define FULLMASK 0xffffffffu

// Problem dims (fixed by the dataset)
#define Bb 16
#define Ss 256
#define Nn 16
#define Dd 6
#define Hh 16
#define CHAINS 256
#define NSEG 16
#define SEGL 16

// Raw local prefixes: [c*256+t][hq][lane] float4 = 128 MB
__device__ float4 g_P[(size_t)CHAINS * Ss * 4 * 32];
// Segment cumulative rotors: [c][hq][s][lane] float4 = 8 MB
__device__ float4 g_C[(size_t)CHAINS * 4 * NSEG * 32];
// Per-(row) projection partials, layout [row][d*16 + head] = 25 MB
__device__ float g_part[(size_t)CHAINS * Ss * 96];

// ---- Clifford sign machinery (5-bit blade masks, matches reference) ----
__host__ __device__ constexpr unsigned popc5(unsigned v) {
    v &= 31u;
    return (v & 1u) + ((v >> 1) & 1u) + ((v >> 2) & 1u) + ((v >> 3) & 1u) + ((v >> 4) & 1u);
}
__host__ __device__ constexpr int csn(unsigned a, unsigned b) {
    a >>= 1; int s = 0;
    while (a) { s += (int)popc5(a & b); a >>= 1; }
    return s & 1;
}
// lift 4-bit even-subalgebra label -> 5-bit even blade mask
__host__ __device__ constexpr unsigned lift4(unsigned L) {
    L &= 15u;
    unsigned p = (L ^ (L >> 1) ^ (L >> 2) ^ (L >> 3)) & 1u;
    return L | (p << 4);
}
// compile-time residual sign table: bit(m*16+s*4+jr) = csn(lift(m*4+s), lift(jr))
__host__ __device__ constexpr unsigned long long buildCT() {
    unsigned long long t = 0;
    for (unsigned m = 0; m < 4; ++m)
        for (unsigned s = 0; s < 4; ++s)
            for (unsigned jr = 0; jr < 4; ++jr)
                if (csn(lift4((m << 2) | s), lift4(jr)))
                    t |= 1ull << (m * 16 + s * 4 + jr);
    return t;
}
static constexpr unsigned long long CT_TABLE = buildCT();
#define CT(m, s, jr) (int)((CT_TABLE >> ((m) * 16 + (s) * 4 + (jr))) & 1ull)

// One mask-m term of out = A*B (16-dim split-ideal XOR-conv).
// dv = A values of group m (sign-corrected by SMC), pm* = B values of group g2^m.
#define GP_MASK(M, dv, SMC, pm0, pm1, pm2, pm3, q0, q1, q2, q3) do {            \
    const float as0 = __uint_as_float(__float_as_uint((dv).x) ^ (SMC)[0]);      \
    const float as1 = __uint_as_float(__float_as_uint((dv).y) ^ (SMC)[1]);      \
    const float as2 = __uint_as_float(__float_as_uint((dv).z) ^ (SMC)[2]);      \
    const float as3 = __uint_as_float(__float_as_uint((dv).w) ^ (SMC)[3]);      \
    q0 = fmaf(CT(M,0,0) ? -as0 : as0, pm0, q0);                                 \
    q1 = fmaf(CT(M,0,1) ? -as0 : as0, pm1, q1);                                 \
    q2 = fmaf(CT(M,0,2) ? -as0 : as0, pm2, q2);                                 \
    q3 = fmaf(CT(M,0,3) ? -as0 : as0, pm3, q3);                                 \
    q0 = fmaf(CT(M,1,1) ? -as1 : as1, pm1, q0);                                 \
    q1 = fmaf(CT(M,1,0) ? -as1 : as1, pm0, q1);                                 \
    q2 = fmaf(CT(M,1,3) ? -as1 : as1, pm3, q2);                                 \
    q3 = fmaf(CT(M,1,2) ? -as1 : as1, pm2, q3);                                 \
    q0 = fmaf(CT(M,2,2) ? -as2 : as2, pm2, q0);                                 \
    q1 = fmaf(CT(M,2,3) ? -as2 : as2, pm3, q1);                                 \
    q2 = fmaf(CT(M,2,0) ? -as2 : as2, pm0, q2);                                 \
    q3 = fmaf(CT(M,2,1) ? -as2 : as2, pm1, q3);                                 \
    q0 = fmaf(CT(M,3,3) ? -as3 : as3, pm3, q0);                                 \
    q1 = fmaf(CT(M,3,2) ? -as3 : as3, pm2, q1);                                 \
    q2 = fmaf(CT(M,3,1) ? -as3 : as3, pm1, q2);                                 \
    q3 = fmaf(CT(M,3,0) ? -as3 : as3, pm0, q3);                                 \
} while (0)

// runtime sign masks for the A-operand's group-m slice vs B-group (g2^m)
__device__ __forceinline__ void build_smC(int g2, unsigned smC[4][4]) {
#pragma unroll
    for (int m = 0; m < 4; ++m) {
        const unsigned jhi = lift4((unsigned)(((g2 ^ m) & 3) << 2));
#pragma unroll
        for (int s = 0; s < 4; ++s)
            smC[m][s] = (unsigned)csn(lift4((unsigned)((m << 2) | s)), jhi) << 31;
    }
}

// ---------------------------------------------------------------------------
// K1: per-segment raw local prefixes P_{s,i} = dl_{s16+i} * ... * dl_{s16}.
// Warp = (chain, headquad, segment); 16384 warps. No normalization (fp32-safe).
// ---------------------------------------------------------------------------
__global__ void __launch_bounds__(256) seg_kernel(
    const float* __restrict__ x,      // [B,S,N,D]
    const float* __restrict__ W_in,   // [D, H*32]
    const float* __restrict__ b_in)   // [H*32]
{
    __shared__ float4 sbuf[2][8][2][32];   // [buf][warp][0=w,1=dl][lane]

    const int gw   = blockIdx.x * 8 + ((threadIdx.x >> 5) & 7);  // 0..16383
    const int wid  = (threadIdx.x >> 5) & 7;
    const int lane = threadIdx.x & 31;
    const int c   = gw >> 6;
    const int hq  = (gw >> 4) & 3;
    const int seg = gw & 15;
    const int hw   = lane >> 3;
    const int half = (lane >> 2) & 1;
    const int g2   = lane & 3;
    const int h  = hq * 4 + hw;
    const int b  = c >> 4;
    const int n  = c & (Nn - 1);
    const int dlbase = lane & 28;

    // inline duality-transformed input weights
    float wi[4][Dd], bi[4];
#pragma unroll
    for (int r = 0; r < 4; ++r) {
        const unsigned E  = lift4((unsigned)(g2 * 4 + r));
        const unsigned Ed = E ^ 31u;
        const float sIn  = csn(31u, Ed) ? -1.0f : 1.0f;
        const float coef = half ? -sIn : sIn;
        const int colE = h * 32 + (int)E, colD = h * 32 + (int)Ed;
#pragma unroll
        for (int d = 0; d < Dd; ++d)
            wi[r][d] = __ldg(W_in + d * 512 + colE) + coef * __ldg(W_in + d * 512 + colD);
        bi[r] = __ldg(b_in + colE) + coef * __ldg(b_in + colD);
    }
    unsigned smC[4][4];
    build_smC(g2, smC);

    // local prefix state = identity
    float w0 = (g2 == 0) ? 1.0f : 0.0f, w1 = 0.f, w2 = 0.f, w3 = 0.f;

    const float* xp = x + (((size_t)b * Ss + seg * SEGL) * Nn + n) * Dd;
    float4* pp = g_P + (((size_t)(c * Ss + seg * SEGL)) * 4 + hq) * 32 + lane;

    float cx[Dd];
#pragma unroll
    for (int d = 0; d < Dd; ++d) cx[d] = __ldg(xp + d);

#pragma unroll 1
    for (int i = 0; i < SEGL; ++i) {
        const int buf = i & 1;
        const float* xn = xp + Nn * Dd;
        const bool more = (i + 1 < SEGL);
        float nx[Dd];
#pragma unroll
        for (int d = 0; d < Dd; ++d) nx[d] = more ? __ldg(xn + d) : 0.0f;

        // dl = transformed (x@W_in + b_in ; +1 at label 0)
        float dl0 = bi[0], dl1 = bi[1], dl2 = bi[2], dl3 = bi[3];
#pragma unroll
        for (int d = 0; d < Dd; ++d) {
            dl0 = fmaf(wi[0][d], cx[d], dl0);
            dl1 = fmaf(wi[1][d], cx[d], dl1);
            dl2 = fmaf(wi[2][d], cx[d], dl2);
            dl3 = fmaf(wi[3][d], cx[d], dl3);
        }
        if (g2 == 0) dl0 += 1.0f;

        sbuf[buf][wid][0][lane] = make_float4(w0, w1, w2, w3);
        sbuf[buf][wid][1][lane] = make_float4(dl0, dl1, dl2, dl3);
        __syncwarp();

        float pA0 = 0.f, pA1 = 0.f, pA2 = 0.f, pA3 = 0.f;
        float pB0 = 0.f, pB1 = 0.f, pB2 = 0.f, pB3 = 0.f;
        {   // m = 0 (B-side local)
            const float4 dv = sbuf[buf][wid][1][dlbase];
            GP_MASK(0, dv, smC[0], w0, w1, w2, w3, pA0, pA1, pA2, pA3);
        }
        {   const float4 wv = sbuf[buf][wid][0][lane ^ 1];
            const float4 dv = sbuf[buf][wid][1][dlbase | 1];
            GP_MASK(1, dv, smC[1], wv.x, wv.y, wv.z, wv.w, pB0, pB1, pB2, pB3);
        }
        {   const float4 wv = sbuf[buf][wid][0][lane ^ 2];
            const float4 dv = sbuf[buf][wid][1][dlbase | 2];
            GP_MASK(2, dv, smC[2], wv.x, wv.y, wv.z, wv.w, pA0, pA1, pA2, pA3);
        }
        {   const float4 wv = sbuf[buf][wid][0][lane ^ 3];
            const float4 dv = sbuf[buf][wid][1][dlbase | 3];
            GP_MASK(3, dv, smC[3], wv.x, wv.y, wv.z, wv.w, pB0, pB1, pB2, pB3);
        }
        w0 = pA0 + pB0; w1 = pA1 + pB1; w2 = pA2 + pB2; w3 = pA3 + pB3;

        *pp = make_float4(w0, w1, w2, w3);    // raw local prefix
        pp += 4 * 32;
        xp = xn;
#pragma unroll
        for (int d = 0; d < Dd; ++d) cx[d] = nx[d];
    }
}

// ---------------------------------------------------------------------------
// K2: scan of segment totals. Warp = (chain, headquad); 1024 warps.
// C_{s+1} = normalize(T_s * C_s); T_s = g_P[t = s*16+15].
// ---------------------------------------------------------------------------
__global__ void __launch_bounds__(256) scan_kernel()
{
    __shared__ float4 sbuf[2][8][2][32];

    const int gw   = blockIdx.x * 8 + ((threadIdx.x >> 5) & 7);  // 0..1023
    const int wid  = (threadIdx.x >> 5) & 7;
    const int lane = threadIdx.x & 31;
    const int c  = gw >> 2;
    const int hq = gw & 3;
    const int g2 = lane & 3;
    const int dlbase = lane & 28;

    unsigned smC[4][4];
    build_smC(g2, smC);

    float c0 = (g2 == 0) ? 1.0f : 0.0f, c1 = 0.f, c2 = 0.f, c3 = 0.f;

    float4* pC = g_C + (((size_t)(c * 4 + hq)) * NSEG) * 32 + lane;

#pragma unroll 1
    for (int s = 0; s < NSEG; ++s) {
        const int buf = s & 1;
        pC[s * 32] = make_float4(c0, c1, c2, c3);      // C_s

        const float4 T = g_P[(((size_t)(c * Ss + s * SEGL + SEGL - 1)) * 4 + hq) * 32 + lane];

        sbuf[buf][wid][0][lane] = make_float4(c0, c1, c2, c3);
        sbuf[buf][wid][1][lane] = T;
        __syncwarp();

        float pA0 = 0.f, pA1 = 0.f, pA2 = 0.f, pA3 = 0.f;
        float pB0 = 0.f, pB1 = 0.f, pB2 = 0.f, pB3 = 0.f;
        {   const float4 dv = sbuf[buf][wid][1][dlbase];
            GP_MASK(0, dv, smC[0], c0, c1, c2, c3, pA0, pA1, pA2, pA3);
        }
        {   const float4 wv = sbuf[buf][wid][0][lane ^ 1];
            const float4 dv = sbuf[buf][wid][1][dlbase | 1];
            GP_MASK(1, dv, smC[1], wv.x, wv.y, wv.z, wv.w, pB0, pB1, pB2, pB3);
        }
        {   const float4 wv = sbuf[buf][wid][0][lane ^ 2];
            const float4 dv = sbuf[buf][wid][1][dlbase | 2];
            GP_MASK(2, dv, smC[2], wv.x, wv.y, wv.z, wv.w, pA0, pA1, pA2, pA3);
        }
        {   const float4 wv = sbuf[buf][wid][0][lane ^ 3];
            const float4 dv = sbuf[buf][wid][1][dlbase | 3];
            GP_MASK(3, dv, smC[3], wv.x, wv.y, wv.z, wv.w, pB0, pB1, pB2, pB3);
        }
        float n0 = pA0 + pB0, n1 = pA1 + pB1, n2 = pA2 + pB2, n3 = pA3 + pB3;

        // scale-only normalize (direction exact; keeps magnitudes bounded)
        float ss = n0 * n0 + n1 * n1;
        ss = fmaf(n2, n2, ss);
        ss = fmaf(n3, n3, ss);
        ss += __shfl_xor_sync(FULLMASK, ss, 1);
        ss += __shfl_xor_sync(FULLMASK, ss, 2);
        ss += __shfl_xor_sync(FULLMASK, ss, 4);
        const float r = rsqrtf(ss + 1e-30f);
        c0 = n0 * r; c1 = n1 * r; c2 = n2 * r; c3 = n3 * r;
    }
}

// ---------------------------------------------------------------------------
// K3: apply cumulative rotor + exact normalize + fused projection.
// Warp = (chain, headquad, segment); 16384 warps.
// psi_t = P_{s,i} * C_s  (C in registers, P via smem exchange).
// ---------------------------------------------------------------------------
__global__ void __launch_bounds__(256) apply_kernel(
    const float* __restrict__ W_out)  // [H*32, D]
{
    __shared__ float4 sbuf[2][8][32];   // [buf][warp][lane] for P only

    const int gw   = blockIdx.x * 8 + ((threadIdx.x >> 5) & 7);  // 0..16383
    const int wid  = (threadIdx.x >> 5) & 7;
    const int lane = threadIdx.x & 31;
    const int c   = gw >> 6;
    const int hq  = (gw >> 4) & 3;
    const int seg = gw & 15;
    const int hw   = lane >> 3;
    const int half = (lane >> 2) & 1;
    const int g2   = lane & 3;
    const int h  = hq * 4 + hw;
    const int dlbase = lane & 28;

    // inline duality-transformed output weights
    float wo[4][Dd];
#pragma unroll
    for (int r = 0; r < 4; ++r) {
        const unsigned E  = lift4((unsigned)(g2 * 4 + r));
        const unsigned Ed = E ^ 31u;
        const float sOut = csn(31u, E) ? -1.0f : 1.0f;
        const float coef = half ? -sOut : sOut;
        const int colE = h * 32 + (int)E, colD = h * 32 + (int)Ed;
#pragma unroll
        for (int d = 0; d < Dd; ++d)
            wo[r][d] = __ldg(W_out + colE * Dd + d) + coef * __ldg(W_out + colD * Dd + d);
    }
    unsigned smC[4][4];
    build_smC(g2, smC);

    // load C_s for all 4 xor-neighbors into registers (B-side operand)
    float4 Creg[4];
    {
        const float4* pC = g_C + (((size_t)(c * 4 + hq)) * NSEG + seg) * 32;
#pragma unroll
        for (int m = 0; m < 4; ++m) Creg[m] = __ldg(pC + (lane ^ m));
    }

    const float4* pP = g_P + (((size_t)(c * Ss + seg * SEGL)) * 4 + hq) * 32 + lane;
    float* pw = g_part + ((size_t)(c * Ss + seg * SEGL)) * 96 + (lane & 7) * 16 + h;

#pragma unroll 1
    for (int i = 0; i < SEGL; ++i) {
        const int buf = i & 1;
        const float4 P = __ldg(pP);
        pP += 4 * 32;

        sbuf[buf][wid][lane] = P;
        __syncwarp();

        float pA0 = 0.f, pA1 = 0.f, pA2 = 0.f, pA3 = 0.f;
        float pB0 = 0.f, pB1 = 0.f, pB2 = 0.f, pB3 = 0.f;
        {   const float4 dv = sbuf[buf][wid][dlbase];
            GP_MASK(0, dv, smC[0], Creg[0].x, Creg[0].y, Creg[0].z, Creg[0].w,
                    pA0, pA1, pA2, pA3);
        }
        {   const float4 dv = sbuf[buf][wid][dlbase | 1];
            GP_MASK(1, dv, smC[1], Creg[1].x, Creg[1].y, Creg[1].z, Creg[1].w,
                    pB0, pB1, pB2, pB3);
        }
        {   const float4 dv = sbuf[buf][wid][dlbase | 2];
            GP_MASK(2, dv, smC[2], Creg[2].x, Creg[2].y, Creg[2].z, Creg[2].w,
                    pA0, pA1, pA2, pA3);
        }
        {   const float4 dv = sbuf[buf][wid][dlbase | 3];
            GP_MASK(3, dv, smC[3], Creg[3].x, Creg[3].y, Creg[3].z, Creg[3].w,
                    pB0, pB1, pB2, pB3);
        }
        const float nw0 = pA0 + pB0, nw1 = pA1 + pB1;
        const float nw2 = pA2 + pB2, nw3 = pA3 + pB3;

        // exact joint normalize (R8 convention: rn = rsqrt(2*sum + eps), NR step)
        float s = nw0 * nw0 + nw1 * nw1;
        s = fmaf(nw2, nw2, s);
        s = fmaf(nw3, nw3, s);
        s += __shfl_xor_sync(FULLMASK, s, 1);
        s += __shfl_xor_sync(FULLMASK, s, 2);
        s += __shfl_xor_sync(FULLMASK, s, 4);
        s = s + s + 1e-30f;
        float rn = rsqrtf(s);
        rn = rn * (1.5f - 0.5f * s * rn * rn);
        const float st0 = nw0 * rn, st1 = nw1 * rn;
        const float st2 = nw2 * rn, st3 = nw3 * rn;

        // projection partials
        float p0, p1, p2, p3, p4, p5;
        p0 = st0 * wo[0][0]; p1 = st0 * wo[0][1]; p2 = st0 * wo[0][2];
        p3 = st0 * wo[0][3]; p4 = st0 * wo[0][4]; p5 = st0 * wo[0][5];
        p0 = fmaf(st1, wo[1][0], p0); p1 = fmaf(st1, wo[1][1], p1);
        p2 = fmaf(st1, wo[1][2], p2); p3 = fmaf(st1, wo[1][3], p3);
        p4 = fmaf(st1, wo[1][4], p4); p5 = fmaf(st1, wo[1][5], p5);
        p0 = fmaf(st2, wo[2][0], p0); p1 = fmaf(st2, wo[2][1], p1);
        p2 = fmaf(st2, wo[2][2], p2); p3 = fmaf(st2, wo[2][3], p3);
        p4 = fmaf(st2, wo[2][4], p4); p5 = fmaf(st2, wo[2][5], p5);
        p0 = fmaf(st3, wo[3][0], p0); p1 = fmaf(st3, wo[3][1], p1);
        p2 = fmaf(st3, wo[3][2], p2); p3 = fmaf(st3, wo[3][3], p3);
        p4 = fmaf(st3, wo[3][4], p4); p5 = fmaf(st3, wo[3][5], p5);
#pragma unroll
        for (int o = 1; o < 8; o <<= 1) {
            p0 += __shfl_xor_sync(FULLMASK, p0, o);
            p1 += __shfl_xor_sync(FULLMASK, p1, o);
            p2 += __shfl_xor_sync(FULLMASK, p2, o);
            p3 += __shfl_xor_sync(FULLMASK, p3, o);
            p4 += __shfl_xor_sync(FULLMASK, p4, o);
            p5 += __shfl_xor_sync(FULLMASK, p5, o);
        }
        const int gg = lane & 7;
        const float pv = (gg == 0) ? p0 : (gg == 1) ? p1 : (gg == 2) ? p2
                       : (gg == 3) ? p3 : (gg == 4) ? p4 : p5;
        if (gg < 6) *pw = pv;
        pw += 96;
    }
}

// ---------------------------------------------------------------------------
// Combine: y[row,d] = x[row,d] + b_out[d] + sum_{16 heads} part
// ---------------------------------------------------------------------------
__global__ void __launch_bounds__(256) combine_kernel(
    const float* __restrict__ x,
    const float* __restrict__ b_out,
    float* __restrict__ y)
{
    const int e   = blockIdx.x * blockDim.x + threadIdx.x;  // 0..393215
    const int row = e / 6;              // chain*256 + t
    const int d   = e - row * 6;

    const float4* pp = (const float4*)(g_part + (size_t)row * 96 + d * 16);
    float4 v0 = __ldg(pp + 0);
    float4 v1 = __ldg(pp + 1);
    float4 v2 = __ldg(pp + 2);
    float4 v3 = __ldg(pp + 3);
    float acc = __ldg(b_out + d)
              + ((v0.x + v0.y) + (v0.z + v0.w))
              + ((v1.x + v1.y) + (v1.z + v1.w))
              + ((v2.x + v2.y) + (v2.z + v2.w))
              + ((v3.x + v3.y) + (v3.z + v3.w));

    const int c = row >> 8;
    const int t = row & (Ss - 1);
    const int b = c >> 4;
    const int n = c & (Nn - 1);
    const size_t off = (((size_t)b * Ss + t) * Nn + n) * Dd + d;
    y[off] = __ldg(x + off) + acc;
}

extern "C" void kernel_launch(void* const* d_in, const int* in_sizes, int n_in,
                              void* d_out, int out_size) {
    const float* x     = (const float*)d_in[0];
    const float* W_in  = (const float*)d_in[1];
    const float* b_in  = (const float*)d_in[2];
    const float* W_out = (const float*)d_in[3];
    const float* b_out = (const float*)d_in[4];
    float* y = (float*)d_out;

    // K1: local prefixes (16384 warps)
    seg_kernel<<<2048, 256>>>(x, W_in, b_in);
    // K2: segment-total scan (1024 warps)
    scan_kernel<<<128, 256>>>();
    // K3: apply + normalize + project (16384 warps)
    apply_kernel<<<2048, 256>>>(W_out);
    // Combine
    combine_kernel<<<1536, 256>>>(x, b_out, y);
}